// round 2
// baseline (speedup 1.0000x reference)
#include <cuda_runtime.h>
#include <math.h>

// Problem constants
constexpr int cB   = 2;
constexpr int cS   = 2048;
constexpr int cD   = 1024;
constexpr int cH   = 16;
constexpr int cHKV = 4;
constexpr int cDK  = 64;
constexpr int cNKV = cHKV * cDK;   // 256
constexpr int cM   = cB * cS;      // 4096 rows for projections

// Scratch (no allocations allowed)
__device__ float g_qh [cB * cS * cD];
__device__ float g_kh [cB * cS * cNKV];
__device__ float g_vh [cB * cS * cNKV];
__device__ float g_att[cB * cS * cD];

// ---------------------------------------------------------------------------
// GEMM + bias: C[M,N] = A[M,K] @ W[K,N] + bias[N]
// 64x64 block tile, BK=16, 256 threads, 4x4 register tile per thread.
// M, N multiples of 64; K multiple of 16. All pointers 16B-aligned.
// ---------------------------------------------------------------------------
__global__ __launch_bounds__(256)
void gemm_bias_kernel(const float* __restrict__ A, const float* __restrict__ W,
                      const float* __restrict__ bias, float* __restrict__ C,
                      int M, int N, int K) {
    __shared__ float As[16][68];   // padded: stride 68 floats (16B-aligned rows)
    __shared__ float Ws[16][68];

    const int tid = threadIdx.x;
    const int tx = tid & 15;       // 0..15 -> output column group
    const int ty = tid >> 4;       // 0..15 -> output row group
    const int m0 = blockIdx.y * 64;
    const int n0 = blockIdx.x * 64;

    // A-tile load mapping: each thread loads one float4 of a 64x16 tile
    const int a_row = tid >> 2;          // 0..63
    const int a_k4  = (tid & 3) * 4;     // 0,4,8,12
    // W-tile load mapping: 16x64 tile, one float4 per thread
    const int w_k   = tid >> 4;          // 0..15
    const int w_n4  = (tid & 15) * 4;    // 0..60

    float acc[4][4];
    #pragma unroll
    for (int i = 0; i < 4; i++)
        #pragma unroll
        for (int j = 0; j < 4; j++) acc[i][j] = 0.f;

    for (int k0 = 0; k0 < K; k0 += 16) {
        float4 av = *reinterpret_cast<const float4*>(
            &A[(size_t)(m0 + a_row) * K + k0 + a_k4]);
        float4 wv = *reinterpret_cast<const float4*>(
            &W[(size_t)(k0 + w_k) * N + n0 + w_n4]);

        __syncthreads();   // previous iteration's reads done
        As[a_k4 + 0][a_row] = av.x;
        As[a_k4 + 1][a_row] = av.y;
        As[a_k4 + 2][a_row] = av.z;
        As[a_k4 + 3][a_row] = av.w;
        *reinterpret_cast<float4*>(&Ws[w_k][w_n4]) = wv;
        __syncthreads();

        #pragma unroll
        for (int kk = 0; kk < 16; kk++) {
            float4 a = *reinterpret_cast<const float4*>(&As[kk][ty * 4]);
            float4 w = *reinterpret_cast<const float4*>(&Ws[kk][tx * 4]);
            float af[4] = {a.x, a.y, a.z, a.w};
            float wf[4] = {w.x, w.y, w.z, w.w};
            #pragma unroll
            for (int i = 0; i < 4; i++)
                #pragma unroll
                for (int j = 0; j < 4; j++)
                    acc[i][j] += af[i] * wf[j];
        }
    }

    #pragma unroll
    for (int i = 0; i < 4; i++) {
        const int row = m0 + ty * 4 + i;
        #pragma unroll
        for (int j = 0; j < 4; j++) {
            const int col = n0 + tx * 4 + j;
            C[(size_t)row * N + col] = acc[i][j] + bias[col];
        }
    }
}

// ---------------------------------------------------------------------------
// Causal grouped-query flash attention (fp32, online softmax).
// grid: (S/64, H, B), block: 64 threads. Thread t owns query row qtile*64+t.
// q (64 floats) and accumulator (64 floats) live in registers.
// K/V tiles staged in smem (stride-68 padding); all inner reads broadcast.
// ---------------------------------------------------------------------------
__global__ __launch_bounds__(64)
void attn_kernel(const float* __restrict__ qh, const float* __restrict__ kh,
                 const float* __restrict__ vh, float* __restrict__ out) {
    __shared__ float Ks[64][68];
    __shared__ float Vs[64][68];

    const int tid   = threadIdx.x;
    const int qtile = blockIdx.x;
    const int h     = blockIdx.y;
    const int b     = blockIdx.z;
    const int g     = h >> 2;                 // kv head = h / RATIO
    const int qrow  = qtile * 64 + tid;

    // Load query row into registers
    float4 q4[16];
    const float* qp = qh + ((size_t)(b * cS + qrow)) * cD + h * cDK;
    #pragma unroll
    for (int i = 0; i < 16; i++) q4[i] = reinterpret_cast<const float4*>(qp)[i];

    float acc[64];
    #pragma unroll
    for (int d = 0; d < 64; d++) acc[d] = 0.f;
    float mmax = -3.0e38f;
    float l = 0.f;

    for (int kt0 = 0; kt0 <= qtile; kt0++) {
        __syncthreads();   // previous tile's compute done
        const int kr = kt0 * 64 + tid;
        const float* kp = kh + ((size_t)(b * cS + kr)) * cNKV + g * cDK;
        const float* vp = vh + ((size_t)(b * cS + kr)) * cNKV + g * cDK;
        #pragma unroll
        for (int i = 0; i < 16; i++) {
            float4 kv = reinterpret_cast<const float4*>(kp)[i];
            float4 vv = reinterpret_cast<const float4*>(vp)[i];
            *reinterpret_cast<float4*>(&Ks[tid][i * 4]) = kv;
            *reinterpret_cast<float4*>(&Vs[tid][i * 4]) = vv;
        }
        __syncthreads();

        const int kmax = (kt0 == qtile) ? (tid + 1) : 64;   // causal
        for (int kk = 0; kk < kmax; kk++) {
            float s = 0.f;
            #pragma unroll
            for (int i = 0; i < 16; i++) {
                float4 kv = *reinterpret_cast<const float4*>(&Ks[kk][i * 4]);
                s += q4[i].x * kv.x + q4[i].y * kv.y
                   + q4[i].z * kv.z + q4[i].w * kv.w;
            }
            s *= 0.125f;   // 1/sqrt(64)

            if (s > mmax) {      // rare after warm-up (O(log n) updates)
                float corr = __expf(mmax - s);
                l *= corr;
                #pragma unroll
                for (int d = 0; d < 64; d++) acc[d] *= corr;
                mmax = s;
            }
            float p = __expf(s - mmax);
            l += p;
            #pragma unroll
            for (int i = 0; i < 16; i++) {
                float4 vv = *reinterpret_cast<const float4*>(&Vs[kk][i * 4]);
                acc[i * 4 + 0] += p * vv.x;
                acc[i * 4 + 1] += p * vv.y;
                acc[i * 4 + 2] += p * vv.z;
                acc[i * 4 + 3] += p * vv.w;
            }
        }
    }

    const float inv = 1.f / l;
    float* op = out + ((size_t)(b * cS + qrow)) * cD + h * cDK;
    #pragma unroll
    for (int i = 0; i < 16; i++) {
        float4 o;
        o.x = acc[i * 4 + 0] * inv;
        o.y = acc[i * 4 + 1] * inv;
        o.z = acc[i * 4 + 2] * inv;
        o.w = acc[i * 4 + 3] * inv;
        reinterpret_cast<float4*>(op)[i] = o;
    }
}

// ---------------------------------------------------------------------------
// Launch: q,k,v,mask,Wq,bq,Wk,bk,Wv,bv,Wo,bo  (mask unused: causal is known)
// ---------------------------------------------------------------------------
extern "C" void kernel_launch(void* const* d_in, const int* in_sizes, int n_in,
                              void* d_out, int out_size) {
    const float* q  = (const float*)d_in[0];
    const float* k  = (const float*)d_in[1];
    const float* v  = (const float*)d_in[2];
    const float* Wq = (const float*)d_in[4];
    const float* bq = (const float*)d_in[5];
    const float* Wk = (const float*)d_in[6];
    const float* bk = (const float*)d_in[7];
    const float* Wv = (const float*)d_in[8];
    const float* bv = (const float*)d_in[9];
    const float* Wo = (const float*)d_in[10];
    const float* bo = (const float*)d_in[11];
    float* out = (float*)d_out;

    float *qh, *kh, *vh, *att;
    cudaGetSymbolAddress((void**)&qh,  g_qh);
    cudaGetSymbolAddress((void**)&kh,  g_kh);
    cudaGetSymbolAddress((void**)&vh,  g_vh);
    cudaGetSymbolAddress((void**)&att, g_att);

    // Projections
    gemm_bias_kernel<<<dim3(cD   / 64, cM / 64), 256>>>(q, Wq, bq, qh, cM, cD,   cD);
    gemm_bias_kernel<<<dim3(cNKV / 64, cM / 64), 256>>>(k, Wk, bk, kh, cM, cNKV, cD);
    gemm_bias_kernel<<<dim3(cNKV / 64, cM / 64), 256>>>(v, Wv, bv, vh, cM, cNKV, cD);

    // Causal GQA attention
    attn_kernel<<<dim3(cS / 64, cH, cB), 64>>>(qh, kh, vh, att);

    // Output projection
    gemm_bias_kernel<<<dim3(cD / 64, cM / 64), 256>>>(att, Wo, bo, out, cM, cD, cD);
}

// round 3
// speedup vs baseline: 1.0729x; 1.0729x over previous
#include <cuda_runtime.h>
#include <math.h>

// Problem constants
constexpr int cB   = 2;
constexpr int cS   = 2048;
constexpr int cD   = 1024;
constexpr int cH   = 16;
constexpr int cHKV = 4;
constexpr int cDK  = 64;
constexpr int cNKV = cHKV * cDK;   // 256
constexpr int cM   = cB * cS;      // 4096 rows for projections

// Scratch (no allocations allowed)
__device__ float g_qh [cB * cS * cD];
__device__ float g_kh [cB * cS * cNKV];
__device__ float g_vh [cB * cS * cNKV];
__device__ float g_att[cB * cS * cD];

// ---------------------------------------------------------------------------
// GEMM + bias v2: C[M,N] = A[M,K] @ W[K,N] + bias[N]
// 128x128 block tile, BK=16, 256 threads, 8x8 register microtile,
// double-buffered shared memory, one __syncthreads per K-tile.
// Requires: M%128==0, N%128==0, K%16==0, 16B-aligned pointers.
// ---------------------------------------------------------------------------
__global__ __launch_bounds__(256)
void gemm_bias_v2(const float* __restrict__ A, const float* __restrict__ W,
                  const float* __restrict__ bias, float* __restrict__ C,
                  int M, int N, int K) {
    __shared__ float As[2][16][132];   // A^T tile, padded rows (128+4)
    __shared__ float Bs[2][16][128];   // B tile

    const int tid = threadIdx.x;
    const int tx  = tid & 15;          // 0..15 -> n-group
    const int ty  = tid >> 4;          // 0..15 -> m-group
    const int m0  = blockIdx.y * 128;
    const int n0  = blockIdx.x * 128;

    // A-tile: 128x16 floats = 512 float4, 2 per thread (j = tid, tid+256)
    const int a_row0 = tid >> 2;           // 0..63
    const int a_col4 = (tid & 3) * 4;      // 0,4,8,12
    // B-tile: 16x128 floats = 512 float4, 2 per thread
    const int b_row0 = tid >> 5;           // 0..7
    const int b_col  = (tid & 31) * 4;     // 0..124

    const float* Aptr0 = A + (size_t)(m0 + a_row0)      * K + a_col4;
    const float* Aptr1 = A + (size_t)(m0 + a_row0 + 64) * K + a_col4;
    const float* Bptr0 = W + (size_t)(b_row0)     * N + n0 + b_col;
    const float* Bptr1 = W + (size_t)(b_row0 + 8) * N + n0 + b_col;

    float acc[8][8];
    #pragma unroll
    for (int i = 0; i < 8; i++)
        #pragma unroll
        for (int j = 0; j < 8; j++) acc[i][j] = 0.f;

    const int nt = K / 16;

    // Prologue: load tile 0 into buffer 0
    {
        float4 a0 = *reinterpret_cast<const float4*>(Aptr0);
        float4 a1 = *reinterpret_cast<const float4*>(Aptr1);
        float4 w0 = *reinterpret_cast<const float4*>(Bptr0);
        float4 w1 = *reinterpret_cast<const float4*>(Bptr1);
        As[0][a_col4 + 0][a_row0]      = a0.x;
        As[0][a_col4 + 1][a_row0]      = a0.y;
        As[0][a_col4 + 2][a_row0]      = a0.z;
        As[0][a_col4 + 3][a_row0]      = a0.w;
        As[0][a_col4 + 0][a_row0 + 64] = a1.x;
        As[0][a_col4 + 1][a_row0 + 64] = a1.y;
        As[0][a_col4 + 2][a_row0 + 64] = a1.z;
        As[0][a_col4 + 3][a_row0 + 64] = a1.w;
        *reinterpret_cast<float4*>(&Bs[0][b_row0][b_col])     = w0;
        *reinterpret_cast<float4*>(&Bs[0][b_row0 + 8][b_col]) = w1;
    }
    __syncthreads();

    for (int t = 0; t < nt; t++) {
        const int cur = t & 1;
        float4 a0, a1, w0, w1;
        if (t + 1 < nt) {
            const size_t ko = (size_t)(t + 1) * 16;
            a0 = *reinterpret_cast<const float4*>(Aptr0 + ko);
            a1 = *reinterpret_cast<const float4*>(Aptr1 + ko);
            w0 = *reinterpret_cast<const float4*>(Bptr0 + ko * N);
            w1 = *reinterpret_cast<const float4*>(Bptr1 + ko * N);
        }

        #pragma unroll
        for (int kk = 0; kk < 16; kk++) {
            float4 am0 = *reinterpret_cast<const float4*>(&As[cur][kk][ty * 4]);
            float4 am1 = *reinterpret_cast<const float4*>(&As[cur][kk][64 + ty * 4]);
            float4 bn0 = *reinterpret_cast<const float4*>(&Bs[cur][kk][tx * 4]);
            float4 bn1 = *reinterpret_cast<const float4*>(&Bs[cur][kk][64 + tx * 4]);
            float af[8] = {am0.x, am0.y, am0.z, am0.w, am1.x, am1.y, am1.z, am1.w};
            float bf[8] = {bn0.x, bn0.y, bn0.z, bn0.w, bn1.x, bn1.y, bn1.z, bn1.w};
            #pragma unroll
            for (int i = 0; i < 8; i++)
                #pragma unroll
                for (int j = 0; j < 8; j++)
                    acc[i][j] += af[i] * bf[j];
        }

        if (t + 1 < nt) {
            const int nxt = cur ^ 1;
            As[nxt][a_col4 + 0][a_row0]      = a0.x;
            As[nxt][a_col4 + 1][a_row0]      = a0.y;
            As[nxt][a_col4 + 2][a_row0]      = a0.z;
            As[nxt][a_col4 + 3][a_row0]      = a0.w;
            As[nxt][a_col4 + 0][a_row0 + 64] = a1.x;
            As[nxt][a_col4 + 1][a_row0 + 64] = a1.y;
            As[nxt][a_col4 + 2][a_row0 + 64] = a1.z;
            As[nxt][a_col4 + 3][a_row0 + 64] = a1.w;
            *reinterpret_cast<float4*>(&Bs[nxt][b_row0][b_col])     = w0;
            *reinterpret_cast<float4*>(&Bs[nxt][b_row0 + 8][b_col]) = w1;
        }
        __syncthreads();
    }

    // Epilogue: 8x8 per thread, float4 stores, + bias
    float4 bias0 = *reinterpret_cast<const float4*>(&bias[n0 + tx * 4]);
    float4 bias1 = *reinterpret_cast<const float4*>(&bias[n0 + 64 + tx * 4]);
    #pragma unroll
    for (int half = 0; half < 2; half++) {
        #pragma unroll
        for (int i = 0; i < 4; i++) {
            const int row = m0 + half * 64 + ty * 4 + i;
            const int ai  = half * 4 + i;
            float4 o0, o1;
            o0.x = acc[ai][0] + bias0.x;
            o0.y = acc[ai][1] + bias0.y;
            o0.z = acc[ai][2] + bias0.z;
            o0.w = acc[ai][3] + bias0.w;
            o1.x = acc[ai][4] + bias1.x;
            o1.y = acc[ai][5] + bias1.y;
            o1.z = acc[ai][6] + bias1.z;
            o1.w = acc[ai][7] + bias1.w;
            *reinterpret_cast<float4*>(&C[(size_t)row * N + n0 + tx * 4])      = o0;
            *reinterpret_cast<float4*>(&C[(size_t)row * N + n0 + 64 + tx * 4]) = o1;
        }
    }
}

// ---------------------------------------------------------------------------
// Causal grouped-query flash attention v2 (fp32, online softmax).
// grid: (S/128, H, B), block: 128 threads. Thread t owns query row bx*128+t.
// QK dot uses 4 independent accumulators (chain depth 16 instead of 64).
// Scale 1/sqrt(dk) folded into q registers at load.
// ---------------------------------------------------------------------------
__global__ __launch_bounds__(128)
void attn_kernel_v2(const float* __restrict__ qh, const float* __restrict__ kh,
                    const float* __restrict__ vh, float* __restrict__ out) {
    __shared__ float Ks[64][68];
    __shared__ float Vs[64][68];

    const int tid  = threadIdx.x;
    const int bx   = blockIdx.x;
    const int h    = blockIdx.y;
    const int b    = blockIdx.z;
    const int g    = h >> 2;                  // kv head
    const int qrow = bx * 128 + tid;

    // Load query row, pre-scaled by 1/sqrt(64)
    float4 q4[16];
    const float* qp = qh + ((size_t)(b * cS + qrow)) * cD + h * cDK;
    #pragma unroll
    for (int i = 0; i < 16; i++) {
        float4 v = reinterpret_cast<const float4*>(qp)[i];
        v.x *= 0.125f; v.y *= 0.125f; v.z *= 0.125f; v.w *= 0.125f;
        q4[i] = v;
    }

    float acc[64];
    #pragma unroll
    for (int d = 0; d < 64; d++) acc[d] = 0.f;
    float mmax = -3.0e38f;
    float l = 0.f;

    // K/V tile load mapping: thread loads half of row (tid>>1), cols (tid&1)*32..+31
    const int ld_row  = tid >> 1;
    const int ld_coff = (tid & 1) * 32;

    const int nkt = bx * 2 + 2;               // key tiles: [0, bx*2+1]
    for (int kt = 0; kt < nkt; kt++) {
        __syncthreads();                      // previous tile's compute done
        const int kr = kt * 64 + ld_row;
        const float* kp = kh + ((size_t)(b * cS + kr)) * cNKV + g * cDK + ld_coff;
        const float* vp = vh + ((size_t)(b * cS + kr)) * cNKV + g * cDK + ld_coff;
        #pragma unroll
        for (int i = 0; i < 8; i++) {
            *reinterpret_cast<float4*>(&Ks[ld_row][ld_coff + i * 4]) =
                reinterpret_cast<const float4*>(kp)[i];
            *reinterpret_cast<float4*>(&Vs[ld_row][ld_coff + i * 4]) =
                reinterpret_cast<const float4*>(vp)[i];
        }
        __syncthreads();

        const int rel  = qrow - kt * 64;                 // causal offset
        const int kmax = rel >= 64 ? 64 : (rel < 0 ? 0 : rel + 1);

        for (int kk = 0; kk < kmax; kk++) {
            // 4 independent accumulation chains (x/y/z/w lanes)
            float sx = 0.f, sy = 0.f, sz = 0.f, sw = 0.f;
            #pragma unroll
            for (int i = 0; i < 16; i++) {
                float4 kv = *reinterpret_cast<const float4*>(&Ks[kk][i * 4]);
                sx += q4[i].x * kv.x;
                sy += q4[i].y * kv.y;
                sz += q4[i].z * kv.z;
                sw += q4[i].w * kv.w;
            }
            const float s = (sx + sy) + (sz + sw);

            if (s > mmax) {                   // rare after warm-up
                float corr = __expf(mmax - s);
                l *= corr;
                #pragma unroll
                for (int d = 0; d < 64; d++) acc[d] *= corr;
                mmax = s;
            }
            float p = __expf(s - mmax);
            l += p;
            #pragma unroll
            for (int i = 0; i < 16; i++) {
                float4 vv = *reinterpret_cast<const float4*>(&Vs[kk][i * 4]);
                acc[i * 4 + 0] += p * vv.x;
                acc[i * 4 + 1] += p * vv.y;
                acc[i * 4 + 2] += p * vv.z;
                acc[i * 4 + 3] += p * vv.w;
            }
        }
    }

    const float inv = 1.f / l;
    float* op = out + ((size_t)(b * cS + qrow)) * cD + h * cDK;
    #pragma unroll
    for (int i = 0; i < 16; i++) {
        float4 o;
        o.x = acc[i * 4 + 0] * inv;
        o.y = acc[i * 4 + 1] * inv;
        o.z = acc[i * 4 + 2] * inv;
        o.w = acc[i * 4 + 3] * inv;
        reinterpret_cast<float4*>(op)[i] = o;
    }
}

// ---------------------------------------------------------------------------
// Launch: q,k,v,mask,Wq,bq,Wk,bk,Wv,bv,Wo,bo  (mask unused: causal is known)
// ---------------------------------------------------------------------------
extern "C" void kernel_launch(void* const* d_in, const int* in_sizes, int n_in,
                              void* d_out, int out_size) {
    const float* q  = (const float*)d_in[0];
    const float* k  = (const float*)d_in[1];
    const float* v  = (const float*)d_in[2];
    const float* Wq = (const float*)d_in[4];
    const float* bq = (const float*)d_in[5];
    const float* Wk = (const float*)d_in[6];
    const float* bk = (const float*)d_in[7];
    const float* Wv = (const float*)d_in[8];
    const float* bv = (const float*)d_in[9];
    const float* Wo = (const float*)d_in[10];
    const float* bo = (const float*)d_in[11];
    float* out = (float*)d_out;

    float *qh, *kh, *vh, *att;
    cudaGetSymbolAddress((void**)&qh,  g_qh);
    cudaGetSymbolAddress((void**)&kh,  g_kh);
    cudaGetSymbolAddress((void**)&vh,  g_vh);
    cudaGetSymbolAddress((void**)&att, g_att);

    // Projections (128x128 tiles)
    gemm_bias_v2<<<dim3(cD   / 128, cM / 128), 256>>>(q, Wq, bq, qh, cM, cD,   cD);
    gemm_bias_v2<<<dim3(cNKV / 128, cM / 128), 256>>>(k, Wk, bk, kh, cM, cNKV, cD);
    gemm_bias_v2<<<dim3(cNKV / 128, cM / 128), 256>>>(v, Wv, bv, vh, cM, cNKV, cD);

    // Causal GQA attention
    attn_kernel_v2<<<dim3(cS / 128, cH, cB), 128>>>(qh, kh, vh, att);

    // Output projection
    gemm_bias_v2<<<dim3(cD / 128, cM / 128), 256>>>(att, Wo, bo, out, cM, cD, cD);
}

// round 6
// speedup vs baseline: 2.7201x; 2.5353x over previous
#include <cuda_runtime.h>
#include <math.h>
#include <stdint.h>

// Problem constants
constexpr int cB   = 2;
constexpr int cS   = 2048;
constexpr int cD   = 1024;
constexpr int cH   = 16;
constexpr int cHKV = 4;
constexpr int cDK  = 64;
constexpr int cNKV = cHKV * cDK;   // 256
constexpr int cM   = cB * cS;      // 4096

// Scratch (no allocations allowed)
__device__ float g_qh [cB * cS * cD];
__device__ float g_kh [cB * cS * cNKV];
__device__ float g_vh [cB * cS * cNKV];
__device__ float g_att[cB * cS * cD];

// ---------------------------------------------------------------------------
// tf32 helpers
// ---------------------------------------------------------------------------
__device__ __forceinline__ unsigned f2tf(float f) {
    unsigned u;
    asm("cvt.rna.tf32.f32 %0, %1;" : "=r"(u) : "f"(f));
    return u;
}

// D = A(16x8,row) @ B(8x8,col) + C, tf32 in / f32 out
__device__ __forceinline__ void mma_tf32(float d[4], const unsigned a[4],
                                         unsigned b0, unsigned b1) {
    asm("mma.sync.aligned.m16n8k8.row.col.f32.tf32.tf32.f32 "
        "{%0,%1,%2,%3}, {%4,%5,%6,%7}, {%8,%9}, {%0,%1,%2,%3};"
        : "+f"(d[0]), "+f"(d[1]), "+f"(d[2]), "+f"(d[3])
        : "r"(a[0]), "r"(a[1]), "r"(a[2]), "r"(a[3]), "r"(b0), "r"(b1));
}

// ---------------------------------------------------------------------------
// GEMM + bias via tf32 mma: C[M,N] = A[M,K] @ W[K,N] + bias[N]
// 128x128 block tile, BK=16, 256 threads = 8 warps (2m x 4n), warp tile 64x32.
// Double-buffered smem; fragment LDS bank-conflict-free by padding.
// Requires M%128==0, N%128==0, K%16==0.
// ---------------------------------------------------------------------------
__global__ __launch_bounds__(256)
void gemm_mma(const float* __restrict__ A, const float* __restrict__ W,
              const float* __restrict__ bias, float* __restrict__ C,
              int M, int N, int K) {
    __shared__ __align__(16) unsigned As[2][128][20];   // [m][k], stride 20
    __shared__ __align__(16) unsigned Bs[2][16][136];   // [k][n], stride 136

    const int tid  = threadIdx.x;
    const int w    = tid >> 5;
    const int lane = tid & 31;
    const int g    = lane >> 2;     // groupID 0..7
    const int tg   = lane & 3;      // threadInGroup 0..3
    const int wm   = w & 1;         // 0..1  -> m half (64 rows)
    const int wn   = w >> 1;        // 0..3  -> n quarter (32 cols)
    const int m0   = blockIdx.y * 128;
    const int n0   = blockIdx.x * 128;

    // Load mappings
    const int a_row = tid >> 1;            // 0..127
    const int a_kq  = (tid & 1) * 8;       // 0 or 8
    const int b_row = tid >> 4;            // 0..15
    const int b_col = (tid & 15) * 4;      // 0..60

    const float* Ap = A + (size_t)(m0 + a_row) * K + a_kq;
    const float* Bp0 = W + (size_t)b_row * N + n0 + b_col;
    const float* Bp1 = Bp0 + 64;

    float acc[4][4][4];   // [mi][ni][frag]
    #pragma unroll
    for (int mi = 0; mi < 4; mi++)
        #pragma unroll
        for (int ni = 0; ni < 4; ni++)
            #pragma unroll
            for (int f = 0; f < 4; f++) acc[mi][ni][f] = 0.f;

    const int nt = K / 16;

    // Prologue: tile 0 -> buffer 0
    {
        float4 a0 = *reinterpret_cast<const float4*>(Ap);
        float4 a1 = *reinterpret_cast<const float4*>(Ap + 4);
        float4 w0 = *reinterpret_cast<const float4*>(Bp0);
        float4 w1 = *reinterpret_cast<const float4*>(Bp1);
        uint4 ua0 = {f2tf(a0.x), f2tf(a0.y), f2tf(a0.z), f2tf(a0.w)};
        uint4 ua1 = {f2tf(a1.x), f2tf(a1.y), f2tf(a1.z), f2tf(a1.w)};
        uint4 uw0 = {f2tf(w0.x), f2tf(w0.y), f2tf(w0.z), f2tf(w0.w)};
        uint4 uw1 = {f2tf(w1.x), f2tf(w1.y), f2tf(w1.z), f2tf(w1.w)};
        *reinterpret_cast<uint4*>(&As[0][a_row][a_kq])     = ua0;
        *reinterpret_cast<uint4*>(&As[0][a_row][a_kq + 4]) = ua1;
        *reinterpret_cast<uint4*>(&Bs[0][b_row][b_col])      = uw0;
        *reinterpret_cast<uint4*>(&Bs[0][b_row][b_col + 64]) = uw1;
    }
    __syncthreads();

    for (int t = 0; t < nt; t++) {
        const int cur = t & 1;
        float4 a0, a1, w0, w1;
        if (t + 1 < nt) {
            const size_t ko = (size_t)(t + 1) * 16;
            a0 = *reinterpret_cast<const float4*>(Ap + ko);
            a1 = *reinterpret_cast<const float4*>(Ap + ko + 4);
            w0 = *reinterpret_cast<const float4*>(Bp0 + ko * N);
            w1 = *reinterpret_cast<const float4*>(Bp1 + ko * N);
        }

        #pragma unroll
        for (int kk = 0; kk < 2; kk++) {
            // A fragments: rows wm*64 + 16mi + g(+8), cols 8kk + tg(+4)
            unsigned af[4][4];
            #pragma unroll
            for (int mi = 0; mi < 4; mi++) {
                const int r = wm * 64 + 16 * mi + g;
                af[mi][0] = As[cur][r][8 * kk + tg];
                af[mi][1] = As[cur][r + 8][8 * kk + tg];
                af[mi][2] = As[cur][r][8 * kk + tg + 4];
                af[mi][3] = As[cur][r + 8][8 * kk + tg + 4];
            }
            // B fragments: rows 8kk + tg(+4), cols wn*32 + 8ni + g
            unsigned bf[4][2];
            #pragma unroll
            for (int ni = 0; ni < 4; ni++) {
                const int c = wn * 32 + 8 * ni + g;
                bf[ni][0] = Bs[cur][8 * kk + tg][c];
                bf[ni][1] = Bs[cur][8 * kk + tg + 4][c];
            }
            #pragma unroll
            for (int mi = 0; mi < 4; mi++)
                #pragma unroll
                for (int ni = 0; ni < 4; ni++)
                    mma_tf32(acc[mi][ni], af[mi], bf[ni][0], bf[ni][1]);
        }

        if (t + 1 < nt) {
            const int nxt = cur ^ 1;
            uint4 ua0 = {f2tf(a0.x), f2tf(a0.y), f2tf(a0.z), f2tf(a0.w)};
            uint4 ua1 = {f2tf(a1.x), f2tf(a1.y), f2tf(a1.z), f2tf(a1.w)};
            uint4 uw0 = {f2tf(w0.x), f2tf(w0.y), f2tf(w0.z), f2tf(w0.w)};
            uint4 uw1 = {f2tf(w1.x), f2tf(w1.y), f2tf(w1.z), f2tf(w1.w)};
            *reinterpret_cast<uint4*>(&As[nxt][a_row][a_kq])     = ua0;
            *reinterpret_cast<uint4*>(&As[nxt][a_row][a_kq + 4]) = ua1;
            *reinterpret_cast<uint4*>(&Bs[nxt][b_row][b_col])      = uw0;
            *reinterpret_cast<uint4*>(&Bs[nxt][b_row][b_col + 64]) = uw1;
        }
        __syncthreads();
    }

    // Epilogue: C fragments (rows ..+g, ..+g+8; cols ..+2tg, +2tg+1) + bias
    #pragma unroll
    for (int ni = 0; ni < 4; ni++) {
        const int col = n0 + wn * 32 + 8 * ni + 2 * tg;
        const float2 bv = *reinterpret_cast<const float2*>(&bias[col]);
        #pragma unroll
        for (int mi = 0; mi < 4; mi++) {
            const int r0 = m0 + wm * 64 + 16 * mi + g;
            float2 o0 = {acc[mi][ni][0] + bv.x, acc[mi][ni][1] + bv.y};
            float2 o1 = {acc[mi][ni][2] + bv.x, acc[mi][ni][3] + bv.y};
            *reinterpret_cast<float2*>(&C[(size_t)r0 * N + col])       = o0;
            *reinterpret_cast<float2*>(&C[(size_t)(r0 + 8) * N + col]) = o1;
        }
    }
}

// ---------------------------------------------------------------------------
// Causal GQA flash attention via tf32 mma.
// grid (S/64, H, B), 128 threads = 4 warps; warp w owns query rows 16w..16w+15.
// Q fragments register-resident (x 1/sqrt(dk)); K smem [key][dk] stride 68;
// V smem transposed [dk][key] stride 68. P re-fragmented C->A layout via shfl.
// ---------------------------------------------------------------------------
__global__ __launch_bounds__(128)
void attn_mma(const float* __restrict__ qh, const float* __restrict__ kh,
              const float* __restrict__ vh, float* __restrict__ out) {
    __shared__ __align__(16) unsigned Ks[64][68];   // [key][dk] (also Q staging)
    __shared__ __align__(16) unsigned Vt[64][68];   // [dk][key]

    const int tid  = threadIdx.x;
    const int w    = tid >> 5;
    const int lane = tid & 31;
    const int g    = lane >> 2;
    const int tg   = lane & 3;
    const int bx   = blockIdx.x;
    const int h    = blockIdx.y;
    const int b    = blockIdx.z;
    const int kvh  = h >> 2;
    const int q0   = bx * 64;

    // Stage Q tile (rows q0..q0+63) into Ks, scaled, tf32
    if (tid < 64) {
        const float* qp = qh + ((size_t)(b * cS + q0 + tid)) * cD + h * cDK;
        #pragma unroll
        for (int i = 0; i < 16; i++) {
            float4 v = reinterpret_cast<const float4*>(qp)[i];
            uint4 u = {f2tf(v.x * 0.125f), f2tf(v.y * 0.125f),
                       f2tf(v.z * 0.125f), f2tf(v.w * 0.125f)};
            *reinterpret_cast<uint4*>(&Ks[tid][4 * i]) = u;
        }
    }
    __syncthreads();

    // Q A-fragments: 8 k-steps; rows 16w+g(+8), cols 8ks+tg(+4)
    unsigned qf[8][4];
    #pragma unroll
    for (int ks = 0; ks < 8; ks++) {
        qf[ks][0] = Ks[16 * w + g][8 * ks + tg];
        qf[ks][1] = Ks[16 * w + g + 8][8 * ks + tg];
        qf[ks][2] = Ks[16 * w + g][8 * ks + tg + 4];
        qf[ks][3] = Ks[16 * w + g + 8][8 * ks + tg + 4];
    }

    float O[8][4];
    #pragma unroll
    for (int ni = 0; ni < 8; ni++)
        #pragma unroll
        for (int f = 0; f < 4; f++) O[ni][f] = 0.f;
    float mr0 = -1e30f, mr1 = -1e30f;   // row maxima (rows g, g+8)
    float lr0 = 0.f, lr1 = 0.f;         // row sums

    for (int kt = 0; kt <= bx; kt++) {
        __syncthreads();   // previous tile compute done (also guards Q frag reads)
        // Load K/V tile: threads 0..63 -> V row (transposed store),
        //                threads 64..127 -> K row.
        if (tid < 64) {
            const float* vp = vh + ((size_t)(b * cS + kt * 64 + tid)) * cNKV + kvh * cDK;
            #pragma unroll
            for (int i = 0; i < 16; i++) {
                float4 v = reinterpret_cast<const float4*>(vp)[i];
                Vt[4 * i + 0][tid] = f2tf(v.x);
                Vt[4 * i + 1][tid] = f2tf(v.y);
                Vt[4 * i + 2][tid] = f2tf(v.z);
                Vt[4 * i + 3][tid] = f2tf(v.w);
            }
        } else {
            const int r = tid - 64;
            const float* kp = kh + ((size_t)(b * cS + kt * 64 + r)) * cNKV + kvh * cDK;
            #pragma unroll
            for (int i = 0; i < 16; i++) {
                float4 v = reinterpret_cast<const float4*>(kp)[i];
                uint4 u = {f2tf(v.x), f2tf(v.y), f2tf(v.z), f2tf(v.w)};
                *reinterpret_cast<uint4*>(&Ks[r][4 * i]) = u;
            }
        }
        __syncthreads();

        // S = Q @ K^T : 8 n-tiles of 8 keys
        float S[8][4];
        #pragma unroll
        for (int ni = 0; ni < 8; ni++) {
            S[ni][0] = S[ni][1] = S[ni][2] = S[ni][3] = 0.f;
            #pragma unroll
            for (int ks = 0; ks < 8; ks++) {
                unsigned b0 = Ks[8 * ni + g][8 * ks + tg];
                unsigned b1 = Ks[8 * ni + g][8 * ks + tg + 4];
                mma_tf32(S[ni], qf[ks], b0, b1);
            }
        }

        // Causal mask on diagonal tile (q0 == kt*64: compare in-tile indices)
        if (kt == bx) {
            const int r0 = 16 * w + g, r1 = r0 + 8;
            #pragma unroll
            for (int ni = 0; ni < 8; ni++) {
                const int c0 = 8 * ni + 2 * tg, c1 = c0 + 1;
                if (c0 > r0) S[ni][0] = -1e30f;
                if (c1 > r0) S[ni][1] = -1e30f;
                if (c0 > r1) S[ni][2] = -1e30f;
                if (c1 > r1) S[ni][3] = -1e30f;
            }
        }

        // Online softmax (rows g and g+8 per thread; quad butterfly)
        float mx0 = -1e30f, mx1 = -1e30f;
        #pragma unroll
        for (int ni = 0; ni < 8; ni++) {
            mx0 = fmaxf(mx0, fmaxf(S[ni][0], S[ni][1]));
            mx1 = fmaxf(mx1, fmaxf(S[ni][2], S[ni][3]));
        }
        mx0 = fmaxf(mx0, __shfl_xor_sync(0xffffffffu, mx0, 1));
        mx0 = fmaxf(mx0, __shfl_xor_sync(0xffffffffu, mx0, 2));
        mx1 = fmaxf(mx1, __shfl_xor_sync(0xffffffffu, mx1, 1));
        mx1 = fmaxf(mx1, __shfl_xor_sync(0xffffffffu, mx1, 2));

        const float mn0 = fmaxf(mr0, mx0), mn1 = fmaxf(mr1, mx1);
        const float c0 = __expf(mr0 - mn0), c1 = __expf(mr1 - mn1);
        mr0 = mn0; mr1 = mn1;

        float s0 = 0.f, s1 = 0.f;
        #pragma unroll
        for (int ni = 0; ni < 8; ni++) {
            float p0 = __expf(S[ni][0] - mn0);
            float p1 = __expf(S[ni][1] - mn0);
            float p2 = __expf(S[ni][2] - mn1);
            float p3 = __expf(S[ni][3] - mn1);
            s0 += p0 + p1;
            s1 += p2 + p3;
            // store tf32 bits of P in place
            S[ni][0] = __uint_as_float(f2tf(p0));
            S[ni][1] = __uint_as_float(f2tf(p1));
            S[ni][2] = __uint_as_float(f2tf(p2));
            S[ni][3] = __uint_as_float(f2tf(p3));
        }
        s0 += __shfl_xor_sync(0xffffffffu, s0, 1);
        s0 += __shfl_xor_sync(0xffffffffu, s0, 2);
        s1 += __shfl_xor_sync(0xffffffffu, s1, 1);
        s1 += __shfl_xor_sync(0xffffffffu, s1, 2);
        lr0 = lr0 * c0 + s0;
        lr1 = lr1 * c1 + s1;
        #pragma unroll
        for (int ni = 0; ni < 8; ni++) {
            O[ni][0] *= c0; O[ni][1] *= c0;
            O[ni][2] *= c1; O[ni][3] *= c1;
        }

        // O += P @ V : for each k-step build P A-frag from C-layout via shfl
        #pragma unroll
        for (int ks = 0; ks < 8; ks++) {
            const int srcA = (lane & ~3) | (tg >> 1);
            const int srcB = srcA + 2;
            float v00 = __shfl_sync(0xffffffffu, S[ks][0], srcA);
            float v01 = __shfl_sync(0xffffffffu, S[ks][1], srcA);
            float v20 = __shfl_sync(0xffffffffu, S[ks][2], srcA);
            float v21 = __shfl_sync(0xffffffffu, S[ks][3], srcA);
            float w00 = __shfl_sync(0xffffffffu, S[ks][0], srcB);
            float w01 = __shfl_sync(0xffffffffu, S[ks][1], srcB);
            float w20 = __shfl_sync(0xffffffffu, S[ks][2], srcB);
            float w21 = __shfl_sync(0xffffffffu, S[ks][3], srcB);
            const bool odd = (tg & 1) != 0;
            unsigned a[4];
            a[0] = __float_as_uint(odd ? v01 : v00);
            a[1] = __float_as_uint(odd ? v21 : v20);
            a[2] = __float_as_uint(odd ? w01 : w00);
            a[3] = __float_as_uint(odd ? w21 : w20);
            #pragma unroll
            for (int ni = 0; ni < 8; ni++) {
                unsigned b0 = Vt[8 * ni + g][8 * ks + tg];
                unsigned b1 = Vt[8 * ni + g][8 * ks + tg + 4];
                mma_tf32(O[ni], a, b0, b1);
            }
        }
    }

    // Normalize + store
    const float inv0 = 1.f / lr0, inv1 = 1.f / lr1;
    const int r0 = q0 + 16 * w + g;
    float* op0 = out + ((size_t)(b * cS + r0)) * cD + h * cDK;
    float* op1 = op0 + (size_t)8 * cD;
    #pragma unroll
    for (int ni = 0; ni < 8; ni++) {
        float2 o0 = {O[ni][0] * inv0, O[ni][1] * inv0};
        float2 o1 = {O[ni][2] * inv1, O[ni][3] * inv1};
        *reinterpret_cast<float2*>(op0 + 8 * ni + 2 * tg) = o0;
        *reinterpret_cast<float2*>(op1 + 8 * ni + 2 * tg) = o1;
    }
}

// ---------------------------------------------------------------------------
// Launch
// ---------------------------------------------------------------------------
extern "C" void kernel_launch(void* const* d_in, const int* in_sizes, int n_in,
                              void* d_out, int out_size) {
    const float* q  = (const float*)d_in[0];
    const float* k  = (const float*)d_in[1];
    const float* v  = (const float*)d_in[2];
    const float* Wq = (const float*)d_in[4];
    const float* bq = (const float*)d_in[5];
    const float* Wk = (const float*)d_in[6];
    const float* bk = (const float*)d_in[7];
    const float* Wv = (const float*)d_in[8];
    const float* bv = (const float*)d_in[9];
    const float* Wo = (const float*)d_in[10];
    const float* bo = (const float*)d_in[11];
    float* out = (float*)d_out;

    float *qh, *kh, *vh, *att;
    cudaGetSymbolAddress((void**)&qh,  g_qh);
    cudaGetSymbolAddress((void**)&kh,  g_kh);
    cudaGetSymbolAddress((void**)&vh,  g_vh);
    cudaGetSymbolAddress((void**)&att, g_att);

    gemm_mma<<<dim3(cD   / 128, cM / 128), 256>>>(q, Wq, bq, qh, cM, cD,   cD);
    gemm_mma<<<dim3(cNKV / 128, cM / 128), 256>>>(k, Wk, bk, kh, cM, cNKV, cD);
    gemm_mma<<<dim3(cNKV / 128, cM / 128), 256>>>(v, Wv, bv, vh, cM, cNKV, cD);

    attn_mma<<<dim3(cS / 64, cH, cB), 128>>>(qh, kh, vh, att);

    gemm_mma<<<dim3(cD / 128, cM / 128), 256>>>(att, Wo, bo, out, cM, cD, cD);
}